// round 15
// baseline (speedup 1.0000x reference)
#include <cuda_runtime.h>
#include <cuda_bf16.h>
#include <cstdint>

#define B_   8
#define N_   1024
#define C_   768
#define H_   12
#define D_   64
#define BH_  96
#define M_   8192
#define O3_  2304
#define FIXCAP (1 << 21)

// Scratch (static __device__ — no allocation in kernel_launch)
__device__ __align__(16) int8_t g_spk[3][BH_][N_][D_];   // v spikes (tt=2 used)
__device__ __align__(16) __nv_bfloat16 g_qkb[2][BH_][N_][D_]; // q/k spikes bf16
__device__ __align__(16) int8_t g_s[M_][C_];             // post-attention spikes
__device__ int    g_flag[M_];                            // per-row spike flag
__device__ int    g_nfix;                                // uncertain-element count
__device__ int    g_fix_list[FIXCAP];                    // packed m*2304+o
// x hi/lo planes, A-fragment layout: [m_grp 512][k_grp 48][512B tile]
__device__ __align__(16) int8_t g_xhp[512 * 48 * 512];
__device__ __align__(16) int8_t g_xlp[512 * 48 * 512];
// w_qkv hi/lo planes, PAIRED B-fragment layout:
//   [og2 144][k_grp 48][512B tile]
__device__ __align__(16) int8_t g_whp[144 * 48 * 512];
__device__ __align__(16) int8_t g_wlp[144 * 48 * 512];

#define MARGIN 4e-4f

__device__ __forceinline__ int spike_of(float v) {
    float u = v + 0.5f;                        // replicate reference op order
    return (u >= 1.0f) ? 1 : ((u < 0.0f) ? -1 : 0);
}

// ---------------------------------------------------------------------------
// Kernel 1 (merged prep): convert_x + convert_w + init.
// ---------------------------------------------------------------------------
__global__ void __launch_bounds__(256) prep_kernel(const float* __restrict__ x,
                                                   const float* __restrict__ w) {
    if (blockIdx.x < 3072) {
        const int tid = blockIdx.x * 256 + threadIdx.x;   // 786432 total
        if (tid < M_) g_flag[tid] = 0;
        if (tid == 0) g_nfix = 0;
        const int lane = tid & 31;
        const int tile = tid >> 5;                        // 0..24575
        const int kg = tile % 48, mg = tile / 48;
        const int g = lane >> 2, tig = lane & 3;

        uint32_t hw[4], lw[4];
#pragma unroll
        for (int r = 0; r < 4; r++) {
            int m = mg * 16 + (r & 1) * 8 + g;
            int c = kg * 16 + (r >> 1) * 8 + tig * 2;
            float2 v = *(const float2*)(x + (size_t)m * C_ + c);
            __nv_bfloat16 h0 = __float2bfloat16(v.x);
            __nv_bfloat16 l0 = __float2bfloat16(v.x - __bfloat162float(h0));
            __nv_bfloat16 h1 = __float2bfloat16(v.y);
            __nv_bfloat16 l1 = __float2bfloat16(v.y - __bfloat162float(h1));
            __nv_bfloat162 hp; hp.x = h0; hp.y = h1;
            __nv_bfloat162 lp; lp.x = l0; lp.y = l1;
            hw[r] = *(uint32_t*)&hp;
            lw[r] = *(uint32_t*)&lp;
        }
        size_t dst = (size_t)tile * 512 + lane * 16;
        int4 hv, lv;
        hv.x = hw[0]; hv.y = hw[1]; hv.z = hw[2]; hv.w = hw[3];
        lv.x = lw[0]; lv.y = lw[1]; lv.z = lw[2]; lv.w = lw[3];
        *(int4*)(g_xhp + dst) = hv;
        *(int4*)(g_xlp + dst) = lv;
    } else {
        const int tid = (blockIdx.x - 3072) * 256 + threadIdx.x;   // 221184
        const int lane = tid & 31;
        const int tile = tid >> 5;                        // 0..6911
        const int kg = tile % 48, og2 = tile / 48;
        const int oq = lane >> 2, cq = (lane & 3) * 2;

        uint32_t hw[4], lw[4];
#pragma unroll
        for (int half = 0; half < 2; half++) {
            int o = og2 * 16 + half * 8 + oq;
#pragma unroll
            for (int b = 0; b < 2; b++) {
                int c = kg * 16 + b * 8 + cq;
                float2 v = *(const float2*)(w + (size_t)o * C_ + c);
                __nv_bfloat16 h0 = __float2bfloat16(v.x);
                __nv_bfloat16 l0 = __float2bfloat16(v.x - __bfloat162float(h0));
                __nv_bfloat16 h1 = __float2bfloat16(v.y);
                __nv_bfloat16 l1 = __float2bfloat16(v.y - __bfloat162float(h1));
                __nv_bfloat162 hp; hp.x = h0; hp.y = h1;
                __nv_bfloat162 lp; lp.x = l0; lp.y = l1;
                hw[half * 2 + b] = *(uint32_t*)&hp;
                lw[half * 2 + b] = *(uint32_t*)&lp;
            }
        }
        size_t dst = (size_t)tile * 512 + lane * 16;
        int4 hv, lv;
        hv.x = hw[0]; hv.y = hw[1]; hv.z = hw[2]; hv.w = hw[3];
        lv.x = lw[0]; lv.y = lw[1]; lv.z = lw[2]; lv.w = lw[3];
        *(int4*)(g_whp + dst) = hv;
        *(int4*)(g_wlp + dst) = lv;
    }
}

// ---------------------------------------------------------------------------
// Kernel 2: QKV GEMM (R13 plateau form). Epilogue writes bf16 spikes for
// q/k (tt<2) and int8 for v (tt=2).
// ---------------------------------------------------------------------------
#define STG_B   32768
#define QKV_DSMEM 98304

__device__ __forceinline__ void mma_bf16(float* c, const int* a, const int* b) {
    asm volatile("mma.sync.aligned.m16n8k16.row.col.f32.bf16.bf16.f32 "
        "{%0,%1,%2,%3}, {%4,%5,%6,%7}, {%8,%9}, {%0,%1,%2,%3};"
        : "+f"(c[0]), "+f"(c[1]), "+f"(c[2]), "+f"(c[3])
        : "r"(a[0]), "r"(a[1]), "r"(a[2]), "r"(a[3]), "r"(b[0]), "r"(b[1]));
}

__global__ void __launch_bounds__(512, 2) qkv_mma_kernel() {
    extern __shared__ char dyn[];
    uint32_t sbase;
    asm("{ .reg .u64 tmp; cvta.to.shared.u64 tmp, %1; cvt.u32.u64 %0, tmp; }"
        : "=r"(sbase) : "l"(dyn));
    const int t = threadIdx.x, lane = t & 31, wid = t >> 5;
    const int g = lane >> 2, tig = lane & 3;
    const int warpM = wid & 3, warpN = wid >> 2;   // 4 x 4 warps
    const int o0 = blockIdx.x * 128, m0 = blockIdx.y * 128;

    float acc[2][4][4] = {};

#define PREFETCH(st, it) do {                                                  \
    int _s = (st) * STG_B;                                                     \
    int mgl = t >> 6, koff = (t >> 5) & 1;                                     \
    uint32_t slot = (uint32_t)((t & 31) * 16);                                 \
    uint32_t doff = (uint32_t)(mgl * 1024 + koff * 512) + slot;                \
    size_t ga = (size_t)((m0 >> 4) + mgl) * 24576                              \
              + (size_t)((it) * 2 + koff) * 512 + slot;                        \
    size_t gb = (size_t)((o0 >> 4) + mgl) * 24576                              \
              + (size_t)((it) * 2 + koff) * 512 + slot;                        \
    asm volatile("cp.async.cg.shared.global [%0], [%1], 16;"                   \
                 :: "r"(sbase + _s + doff), "l"(g_xhp + ga));                  \
    asm volatile("cp.async.cg.shared.global [%0], [%1], 16;"                   \
                 :: "r"(sbase + _s + 8192 + doff), "l"(g_xlp + ga));           \
    asm volatile("cp.async.cg.shared.global [%0], [%1], 16;"                   \
                 :: "r"(sbase + _s + 16384 + doff), "l"(g_whp + gb));          \
    asm volatile("cp.async.cg.shared.global [%0], [%1], 16;"                   \
                 :: "r"(sbase + _s + 24576 + doff), "l"(g_wlp + gb));          \
    } while (0)

    PREFETCH(0, 0);
    asm volatile("cp.async.commit_group;");
    PREFETCH(1, 1);
    asm volatile("cp.async.commit_group;");

    int stg_idx = 0;
    for (int it = 0; it < 24; it++) {
        if (it < 23) asm volatile("cp.async.wait_group 1;");
        else         asm volatile("cp.async.wait_group 0;");
        __syncthreads();
        if (it + 2 < 24) {
            int pst = stg_idx + 2; if (pst >= 3) pst -= 3;
            PREFETCH(pst, it + 2);
            asm volatile("cp.async.commit_group;");
        }

        const char* stg = dyn + stg_idx * STG_B;
#pragma unroll
        for (int ks = 0; ks < 2; ks++) {
            int ah[2][4], al[2][4];
#pragma unroll
            for (int mi = 0; mi < 2; mi++) {
                uint32_t aoff = (uint32_t)((warpM * 2 + mi) * 1024 + ks * 512
                                           + lane * 16);
                int4 avh = *(const int4*)(stg + aoff);
                int4 avl = *(const int4*)(stg + 8192 + aoff);
                ah[mi][0] = avh.x; ah[mi][1] = avh.y;
                ah[mi][2] = avh.z; ah[mi][3] = avh.w;
                al[mi][0] = avl.x; al[mi][1] = avl.y;
                al[mi][2] = avl.z; al[mi][3] = avl.w;
            }
#pragma unroll
            for (int nip = 0; nip < 2; nip++) {
                uint32_t boff = (uint32_t)((warpN * 2 + nip) * 1024 + ks * 512
                                           + lane * 16);
                int4 bvh = *(const int4*)(stg + 16384 + boff);
                int4 bvl = *(const int4*)(stg + 24576 + boff);
                int bh0[2] = { bvh.x, bvh.y };
                int bh1[2] = { bvh.z, bvh.w };
                int bl0[2] = { bvl.x, bvl.y };
                int bl1[2] = { bvl.z, bvl.w };
#pragma unroll
                for (int mi = 0; mi < 2; mi++) {
                    mma_bf16(acc[mi][nip * 2],     ah[mi], bh0);
                    mma_bf16(acc[mi][nip * 2],     ah[mi], bl0);
                    mma_bf16(acc[mi][nip * 2],     al[mi], bh0);
                    mma_bf16(acc[mi][nip * 2 + 1], ah[mi], bh1);
                    mma_bf16(acc[mi][nip * 2 + 1], ah[mi], bl1);
                    mma_bf16(acc[mi][nip * 2 + 1], al[mi], bh1);
                }
            }
        }
        if (++stg_idx == 3) stg_idx = 0;
    }

    // Epilogue: provisional spikes; uncertain coords pushed to fixup list.
    const int tt = o0 / 768;
    const int hbase = ((o0 % 768) >> 6) + (warpN >> 1);
    const int bh = (m0 >> 10) * H_ + hbase;
    const int nb = (m0 & 1023) + warpM * 32;
#pragma unroll
    for (int mi = 0; mi < 2; mi++) {
#pragma unroll
        for (int ni = 0; ni < 4; ni++) {
            const int col = warpN * 32 + (ni >> 1) * 16 + (ni & 1) * 8 + tig * 2;
            const int d = col & 63;
            int8_t sv[4];
            bool unc[4];
            bool any_unc = false;
#pragma unroll
            for (int e = 0; e < 4; e++) {
                float v = acc[mi][ni][e];
                sv[e] = (int8_t)spike_of(v);
                unc[e] = (fabsf(v - 0.5f) < MARGIN) || (fabsf(v + 0.5f) < MARGIN);
                any_unc |= unc[e];
            }
            if (__any_sync(0xffffffffu, any_unc)) {
#pragma unroll
                for (int e = 0; e < 4; e++) {
                    unsigned msk = __ballot_sync(0xffffffffu, unc[e]);
                    if (msk) {
                        int ldr = __ffs(msk) - 1;
                        int base = 0;
                        if (lane == ldr) base = atomicAdd(&g_nfix, __popc(msk));
                        base = __shfl_sync(0xffffffffu, base, ldr);
                        if (unc[e]) {
                            int mg = m0 + warpM * 32 + mi * 16 + g + ((e >> 1) ? 8 : 0);
                            int og = o0 + col + (e & 1);
                            int pos = base + __popc(msk & ((1u << lane) - 1));
                            if (pos < FIXCAP) g_fix_list[pos] = mg * O3_ + og;
                        }
                    }
                }
            }
            int n1 = nb + mi * 16 + g;
            if (tt == 2) {
                char2 v0, v1;
                v0.x = sv[0]; v0.y = sv[1];
                v1.x = sv[2]; v1.y = sv[3];
                *(char2*)&g_spk[2][bh][n1][d]     = v0;
                *(char2*)&g_spk[2][bh][n1 + 8][d] = v1;
            } else {
                __nv_bfloat162 b0p, b1p;
                b0p.x = __float2bfloat16((float)sv[0]);
                b0p.y = __float2bfloat16((float)sv[1]);
                b1p.x = __float2bfloat16((float)sv[2]);
                b1p.y = __float2bfloat16((float)sv[3]);
                *(__nv_bfloat162*)&g_qkb[tt][bh][n1][d]     = b0p;
                *(__nv_bfloat162*)&g_qkb[tt][bh][n1 + 8][d] = b1p;
            }
        }
    }
}

// ---------------------------------------------------------------------------
// Kernel 3: fixup — exact fp32 warp-dots; writes bf16 for q/k, int8 for v.
// ---------------------------------------------------------------------------
__global__ void __launch_bounds__(256) fixup_kernel(const float* __restrict__ x,
                                                    const float* __restrict__ w) {
    const int lane = threadIdx.x & 31;
    const int gw = (blockIdx.x * blockDim.x + threadIdx.x) >> 5;
    const int nw = (gridDim.x * blockDim.x) >> 5;
    int nfix = g_nfix;
    if (nfix > FIXCAP) nfix = FIXCAP;

    for (int i = gw; i < nfix; i += nw) {
        int code = g_fix_list[i];
        int m = code / O3_;
        int o = code - m * O3_;
        const float4* xp = (const float4*)(x + (size_t)m * C_);
        const float4* wp = (const float4*)(w + (size_t)o * C_);
        float s = 0.0f;
#pragma unroll
        for (int c = 0; c < 6; c++) {
            float4 xv = xp[lane + c * 32];
            float4 wv = wp[lane + c * 32];
            s += xv.x * wv.x + xv.y * wv.y + xv.z * wv.z + xv.w * wv.w;
        }
#pragma unroll
        for (int off = 16; off; off >>= 1)
            s += __shfl_xor_sync(0xffffffffu, s, off);
        if (lane == 0) {
            int tt = o / 768, rem = o - tt * 768;
            int bh = (m >> 10) * H_ + (rem >> 6);
            int sp = spike_of(s);
            if (tt == 2) g_spk[2][bh][m & 1023][rem & 63] = (int8_t)sp;
            else g_qkb[tt][bh][m & 1023][rem & 63] = __float2bfloat16((float)sp);
        }
    }
}

// ---------------------------------------------------------------------------
// Kernel 4 (profiled): FUSED attention, logits on bf16 HMMA (exact for
// ternary spikes). Barrier-free phase 1; B fragments LDG'd from g_qkb[1].
// Dynamic smem: ssq(bf16) 8KB @0, sd 64 x 1040B @8192.
// ---------------------------------------------------------------------------
#define ATTN_DSMEM (8192 + 64 * 1040)

__global__ void __launch_bounds__(256) attn_kernel() {
    extern __shared__ char dyn[];
    char* ssq = dyn;
    char* sd  = dyn + 8192;
    const int t = threadIdx.x;
    const int lane = t & 31, wid = t >> 5;
    const int wg = wid >> 2;          // K-chunk group 0/1
    const int wrp2 = wid & 3;         // warp-in-group (row block)
    const int gid = lane >> 2, tig = lane & 3;
    const int bh = blockIdx.y, n0 = blockIdx.x * 64;
    const int b = bh / H_, h = bh - b * H_;

    {   // ssq: 8KB bf16 q tile
        const int4* src = (const int4*)&g_qkb[0][bh][n0][0];
        ((int4*)ssq)[t] = src[t];
        ((int4*)ssq)[t + 256] = src[t + 256];
    }
    __syncthreads();

    // A fragments: 4 ks-steps of k16 (rows = wrp2*16 + gid/+8)
    int afr[4][4];
#pragma unroll
    for (int ks = 0; ks < 4; ks++) {
        int r = wrp2 * 16 + gid;
        afr[ks][0] = *(const int*)(ssq + r * 128 + ks * 32 + tig * 4);
        afr[ks][1] = *(const int*)(ssq + (r + 8) * 128 + ks * 32 + tig * 4);
        afr[ks][2] = *(const int*)(ssq + r * 128 + ks * 32 + 16 + tig * 4);
        afr[ks][3] = *(const int*)(ssq + (r + 8) * 128 + ks * 32 + 16 + tig * 4);
    }

    // Phase 1: barrier-free; HMMA with B straight from global (L1-hot rows).
    const char* kbase = (const char*)&g_qkb[1][bh][0][0];   // 128 B per k-row
    for (int i = 0; i < 8; i++) {
        const int mc = wg * 8 + i;
#pragma unroll
        for (int c = 0; c < 8; c++) {
            const char* krow = kbase + (size_t)(mc * 64 + c * 8 + gid) * 128;
            float cc[4] = {0.f, 0.f, 0.f, 0.f};
#pragma unroll
            for (int ks = 0; ks < 4; ks++) {
                int bf[2];
                bf[0] = __ldg((const int*)(krow + ks * 32 + tig * 4));
                bf[1] = __ldg((const int*)(krow + ks * 32 + 16 + tig * 4));
                mma_bf16(cc, afr[ks], bf);
            }
            int row = wrp2 * 16 + gid;
            int col = mc * 64 + c * 8 + tig * 2;
            char2 lo; lo.x = (char)(int)cc[0]; lo.y = (char)(int)cc[1];
            char2 hi; hi.x = (char)(int)cc[2]; hi.y = (char)(int)cc[3];
            *(char2*)(sd + row * 1040 + col)       = lo;
            *(char2*)(sd + (row + 8) * 1040 + col) = hi;
        }
    }
    __syncthreads();

    // Phase 2: 8 warps x 8 rows (integer reject; exact path is rare)
    for (int r = 0; r < 8; r++) {
        const int row = wid * 8 + r;
        const char* rp = sd + row * 1040;
        int4 v0 = ((const int4*)rp)[lane];
        int4 v1 = ((const int4*)rp)[lane + 32];
        int words[8] = {v0.x, v0.y, v0.z, v0.w, v1.x, v1.y, v1.z, v1.w};

        int mxw = words[0];
#pragma unroll
        for (int wi = 1; wi < 8; wi++) mxw = __vmaxs4(mxw, words[wi]);
#pragma unroll
        for (int off = 16; off; off >>= 1)
            mxw = __vmaxs4(mxw, __shfl_xor_sync(0xffffffffu, mxw, off));
        int lmax = max(max((mxw << 24) >> 24, (mxw << 16) >> 24),
                       max((mxw << 8) >> 24,  mxw >> 24));

        // strong reject: >=22 elems within 24 of max -> s > 2 -> no spike
        int t24 = lmax - 24;
        int tspl = (t24 & 0xff) * 0x01010101;
        int cnt = 0;
#pragma unroll
        for (int wi = 0; wi < 8; wi++)
            cnt += __popc(__vcmpges4(words[wi], tspl));
#pragma unroll
        for (int off = 16; off; off >>= 1)
            cnt += __shfl_xor_sync(0xffffffffu, cnt, off);

        int* dst = (int*)&g_s[b * N_ + n0 + row][h * D_];
        if (cnt >= 22 * 8) {
            if (lane < 16) dst[lane] = 0;
            continue;
        }

        float s = 0.0f;
        int larg = 0x7fffffff;
#pragma unroll
        for (int wi = 0; wi < 8; wi++) {
            int colbase = (wi < 4) ? (lane * 16 + wi * 4)
                                   : (512 + lane * 16 + (wi - 4) * 4);
#pragma unroll
            for (int j = 0; j < 4; j++) {
                int val = (words[wi] << (24 - 8 * j)) >> 24;
                s += expf(0.125f * (float)(val - lmax));
                if (val == lmax) larg = min(larg, colbase + j);
            }
        }
#pragma unroll
        for (int off = 16; off; off >>= 1) {
            s    += __shfl_xor_sync(0xffffffffu, s, off);
            larg  = min(larg, __shfl_xor_sync(0xffffffffu, larg, off));
        }
        float p = 1.0f / s;
        bool spk = (p + 0.5f) >= 1.0f;
        if (spk) {
            const int* src = (const int*)&g_spk[2][bh][larg][0];
            if (lane < 16) dst[lane] = src[lane];
            if (lane == 0) g_flag[b * N_ + n0 + row] = 1;
        } else {
            if (lane < 16) dst[lane] = 0;
        }
    }
}

// ---------------------------------------------------------------------------
// Kernel 5: output projection (fp32 exact) + final IF, zero-tile skip.
// ---------------------------------------------------------------------------
__global__ void __launch_bounds__(256) proj_kernel(const float* __restrict__ wp,
                                                   float* __restrict__ out) {
    __shared__ float As[16][64];
    __shared__ float Bs[16][64];
    __shared__ int s_any;
    const int t = threadIdx.x;
    const int tx = t & 15, ty = t >> 4;
    const int m0 = blockIdx.y * 64, o0 = blockIdx.x * 64;
    const int lr = t >> 2, lc = (t & 3) * 4;

    if (t == 0) s_any = 0;
    __syncthreads();
    if (t < 64 && g_flag[m0 + t]) s_any = 1;
    __syncthreads();
    if (!s_any) {
        float4 z = make_float4(0.f, 0.f, 0.f, 0.f);
#pragma unroll
        for (int p = 0; p < 4; p++)
            *(float4*)&out[(size_t)(m0 + lr) * 768 + o0 + (t & 3) * 4 + p * 16] = z;
        return;
    }

    float acc[4][4] = {};
    for (int k0 = 0; k0 < 768; k0 += 16) {
        int    aw = *(const int*)&g_s[m0 + lr][k0 + lc];
        float4 bv = *(const float4*)&wp[(size_t)(o0 + lr) * 768 + k0 + lc];
        __syncthreads();
        As[lc + 0][lr] = (float)((aw << 24) >> 24);
        As[lc + 1][lr] = (float)((aw << 16) >> 24);
        As[lc + 2][lr] = (float)((aw << 8)  >> 24);
        As[lc + 3][lr] = (float)( aw        >> 24);
        Bs[lc + 0][lr] = bv.x; Bs[lc + 1][lr] = bv.y;
        Bs[lc + 2][lr] = bv.z; Bs[lc + 3][lr] = bv.w;
        __syncthreads();
#pragma unroll
        for (int k = 0; k < 16; k++) {
            float4 a = *(const float4*)&As[k][ty * 4];
            float4 b = *(const float4*)&Bs[k][tx * 4];
            float ar[4] = {a.x, a.y, a.z, a.w};
            float br[4] = {b.x, b.y, b.z, b.w};
#pragma unroll
            for (int i = 0; i < 4; i++)
#pragma unroll
                for (int j = 0; j < 4; j++)
                    acc[i][j] = fmaf(ar[i], br[j], acc[i][j]);
        }
    }
#pragma unroll
    for (int i = 0; i < 4; i++) {
        int m = m0 + ty * 4 + i;
#pragma unroll
        for (int j = 0; j < 4; j++) {
            int o = o0 + tx * 4 + j;
            out[(size_t)m * 768 + o] = (float)spike_of(acc[i][j]);
        }
    }
}

// ---------------------------------------------------------------------------
extern "C" void kernel_launch(void* const* d_in, const int* in_sizes, int n_in,
                              void* d_out, int out_size) {
    const float* x      = (const float*)d_in[0];
    const float* w_qkv  = (const float*)d_in[1];
    const float* w_proj = (const float*)d_in[2];
    float* out = (float*)d_out;

    cudaFuncSetAttribute(qkv_mma_kernel,
                         cudaFuncAttributeMaxDynamicSharedMemorySize, QKV_DSMEM);
    cudaFuncSetAttribute(attn_kernel,
                         cudaFuncAttributeMaxDynamicSharedMemorySize, ATTN_DSMEM);

    prep_kernel<<<3936, 256>>>(x, w_qkv);                 // launch 1
    qkv_mma_kernel<<<dim3(18, 64), 512, QKV_DSMEM>>>();   // launch 2
    fixup_kernel<<<512, 256>>>(x, w_qkv);                 // launch 3
    attn_kernel<<<dim3(16, 96), 256, ATTN_DSMEM>>>();     // launch 4 (profiled)
    proj_kernel<<<dim3(12, 128), 256>>>(w_proj, out);     // launch 5
}

// round 16
// speedup vs baseline: 1.4131x; 1.4131x over previous
#include <cuda_runtime.h>
#include <cuda_bf16.h>
#include <cstdint>

#define B_   8
#define N_   1024
#define C_   768
#define H_   12
#define D_   64
#define BH_  96
#define M_   8192
#define O3_  2304
#define FIXCAP (1 << 21)

// Scratch (static __device__ — no allocation in kernel_launch)
__device__ __align__(16) int8_t g_spk[3][BH_][N_][D_];   // v spikes (tt=2 used)
__device__ __align__(16) __nv_bfloat16 g_qkb[2][BH_][N_][D_]; // q/k spikes bf16
__device__ __align__(16) int8_t g_s[M_][C_];             // post-attention spikes
__device__ int    g_flag[M_];                            // per-row spike flag
__device__ int    g_nfix;                                // uncertain-element count
__device__ int    g_fix_list[FIXCAP];                    // packed m*2304+o
// x hi/lo planes, A-fragment layout: [m_grp 512][k_grp 48][512B tile]
__device__ __align__(16) int8_t g_xhp[512 * 48 * 512];
__device__ __align__(16) int8_t g_xlp[512 * 48 * 512];
// w_qkv hi/lo planes, PAIRED B-fragment layout: [og2 144][k_grp 48][512B tile]
__device__ __align__(16) int8_t g_whp[144 * 48 * 512];
__device__ __align__(16) int8_t g_wlp[144 * 48 * 512];

#define MARGIN 4e-4f

__device__ __forceinline__ int spike_of(float v) {
    float u = v + 0.5f;                        // replicate reference op order
    return (u >= 1.0f) ? 1 : ((u < 0.0f) ? -1 : 0);
}

// ---------------------------------------------------------------------------
// Kernel 1 (merged prep): convert_x + convert_w + init.
// ---------------------------------------------------------------------------
__global__ void __launch_bounds__(256) prep_kernel(const float* __restrict__ x,
                                                   const float* __restrict__ w) {
    if (blockIdx.x < 3072) {
        const int tid = blockIdx.x * 256 + threadIdx.x;   // 786432 total
        if (tid < M_) g_flag[tid] = 0;
        if (tid == 0) g_nfix = 0;
        const int lane = tid & 31;
        const int tile = tid >> 5;                        // 0..24575
        const int kg = tile % 48, mg = tile / 48;
        const int g = lane >> 2, tig = lane & 3;

        uint32_t hw[4], lw[4];
#pragma unroll
        for (int r = 0; r < 4; r++) {
            int m = mg * 16 + (r & 1) * 8 + g;
            int c = kg * 16 + (r >> 1) * 8 + tig * 2;
            float2 v = *(const float2*)(x + (size_t)m * C_ + c);
            __nv_bfloat16 h0 = __float2bfloat16(v.x);
            __nv_bfloat16 l0 = __float2bfloat16(v.x - __bfloat162float(h0));
            __nv_bfloat16 h1 = __float2bfloat16(v.y);
            __nv_bfloat16 l1 = __float2bfloat16(v.y - __bfloat162float(h1));
            __nv_bfloat162 hp; hp.x = h0; hp.y = h1;
            __nv_bfloat162 lp; lp.x = l0; lp.y = l1;
            hw[r] = *(uint32_t*)&hp;
            lw[r] = *(uint32_t*)&lp;
        }
        size_t dst = (size_t)tile * 512 + lane * 16;
        int4 hv, lv;
        hv.x = hw[0]; hv.y = hw[1]; hv.z = hw[2]; hv.w = hw[3];
        lv.x = lw[0]; lv.y = lw[1]; lv.z = lw[2]; lv.w = lw[3];
        *(int4*)(g_xhp + dst) = hv;
        *(int4*)(g_xlp + dst) = lv;
    } else {
        const int tid = (blockIdx.x - 3072) * 256 + threadIdx.x;   // 221184
        const int lane = tid & 31;
        const int tile = tid >> 5;                        // 0..6911
        const int kg = tile % 48, og2 = tile / 48;
        const int oq = lane >> 2, cq = (lane & 3) * 2;

        uint32_t hw[4], lw[4];
#pragma unroll
        for (int half = 0; half < 2; half++) {
            int o = og2 * 16 + half * 8 + oq;
#pragma unroll
            for (int b = 0; b < 2; b++) {
                int c = kg * 16 + b * 8 + cq;
                float2 v = *(const float2*)(w + (size_t)o * C_ + c);
                __nv_bfloat16 h0 = __float2bfloat16(v.x);
                __nv_bfloat16 l0 = __float2bfloat16(v.x - __bfloat162float(h0));
                __nv_bfloat16 h1 = __float2bfloat16(v.y);
                __nv_bfloat16 l1 = __float2bfloat16(v.y - __bfloat162float(h1));
                __nv_bfloat162 hp; hp.x = h0; hp.y = h1;
                __nv_bfloat162 lp; lp.x = l0; lp.y = l1;
                hw[half * 2 + b] = *(uint32_t*)&hp;
                lw[half * 2 + b] = *(uint32_t*)&lp;
            }
        }
        size_t dst = (size_t)tile * 512 + lane * 16;
        int4 hv, lv;
        hv.x = hw[0]; hv.y = hw[1]; hv.z = hw[2]; hv.w = hw[3];
        lv.x = lw[0]; lv.y = lw[1]; lv.z = lw[2]; lv.w = lw[3];
        *(int4*)(g_whp + dst) = hv;
        *(int4*)(g_wlp + dst) = lv;
    }
}

// ---------------------------------------------------------------------------
// Kernel 2: QKV GEMM (R13 plateau form). Epilogue writes bf16 spikes for
// q/k (tt<2) and int8 for v (tt=2).
// ---------------------------------------------------------------------------
#define STG_B   32768
#define QKV_DSMEM 98304

__device__ __forceinline__ void mma_bf16(float* c, const int* a, const int* b) {
    asm volatile("mma.sync.aligned.m16n8k16.row.col.f32.bf16.bf16.f32 "
        "{%0,%1,%2,%3}, {%4,%5,%6,%7}, {%8,%9}, {%0,%1,%2,%3};"
        : "+f"(c[0]), "+f"(c[1]), "+f"(c[2]), "+f"(c[3])
        : "r"(a[0]), "r"(a[1]), "r"(a[2]), "r"(a[3]), "r"(b[0]), "r"(b[1]));
}

__global__ void __launch_bounds__(512, 2) qkv_mma_kernel() {
    extern __shared__ char dyn[];
    uint32_t sbase;
    asm("{ .reg .u64 tmp; cvta.to.shared.u64 tmp, %1; cvt.u32.u64 %0, tmp; }"
        : "=r"(sbase) : "l"(dyn));
    const int t = threadIdx.x, lane = t & 31, wid = t >> 5;
    const int g = lane >> 2, tig = lane & 3;
    const int warpM = wid & 3, warpN = wid >> 2;   // 4 x 4 warps
    const int o0 = blockIdx.x * 128, m0 = blockIdx.y * 128;

    float acc[2][4][4] = {};

#define PREFETCH(st, it) do {                                                  \
    int _s = (st) * STG_B;                                                     \
    int mgl = t >> 6, koff = (t >> 5) & 1;                                     \
    uint32_t slot = (uint32_t)((t & 31) * 16);                                 \
    uint32_t doff = (uint32_t)(mgl * 1024 + koff * 512) + slot;                \
    size_t ga = (size_t)((m0 >> 4) + mgl) * 24576                              \
              + (size_t)((it) * 2 + koff) * 512 + slot;                        \
    size_t gb = (size_t)((o0 >> 4) + mgl) * 24576                              \
              + (size_t)((it) * 2 + koff) * 512 + slot;                        \
    asm volatile("cp.async.cg.shared.global [%0], [%1], 16;"                   \
                 :: "r"(sbase + _s + doff), "l"(g_xhp + ga));                  \
    asm volatile("cp.async.cg.shared.global [%0], [%1], 16;"                   \
                 :: "r"(sbase + _s + 8192 + doff), "l"(g_xlp + ga));           \
    asm volatile("cp.async.cg.shared.global [%0], [%1], 16;"                   \
                 :: "r"(sbase + _s + 16384 + doff), "l"(g_whp + gb));          \
    asm volatile("cp.async.cg.shared.global [%0], [%1], 16;"                   \
                 :: "r"(sbase + _s + 24576 + doff), "l"(g_wlp + gb));          \
    } while (0)

    PREFETCH(0, 0);
    asm volatile("cp.async.commit_group;");
    PREFETCH(1, 1);
    asm volatile("cp.async.commit_group;");

    int stg_idx = 0;
    for (int it = 0; it < 24; it++) {
        if (it < 23) asm volatile("cp.async.wait_group 1;");
        else         asm volatile("cp.async.wait_group 0;");
        __syncthreads();
        if (it + 2 < 24) {
            int pst = stg_idx + 2; if (pst >= 3) pst -= 3;
            PREFETCH(pst, it + 2);
            asm volatile("cp.async.commit_group;");
        }

        const char* stg = dyn + stg_idx * STG_B;
#pragma unroll
        for (int ks = 0; ks < 2; ks++) {
            int ah[2][4], al[2][4];
#pragma unroll
            for (int mi = 0; mi < 2; mi++) {
                uint32_t aoff = (uint32_t)((warpM * 2 + mi) * 1024 + ks * 512
                                           + lane * 16);
                int4 avh = *(const int4*)(stg + aoff);
                int4 avl = *(const int4*)(stg + 8192 + aoff);
                ah[mi][0] = avh.x; ah[mi][1] = avh.y;
                ah[mi][2] = avh.z; ah[mi][3] = avh.w;
                al[mi][0] = avl.x; al[mi][1] = avl.y;
                al[mi][2] = avl.z; al[mi][3] = avl.w;
            }
#pragma unroll
            for (int nip = 0; nip < 2; nip++) {
                uint32_t boff = (uint32_t)((warpN * 2 + nip) * 1024 + ks * 512
                                           + lane * 16);
                int4 bvh = *(const int4*)(stg + 16384 + boff);
                int4 bvl = *(const int4*)(stg + 24576 + boff);
                int bh0[2] = { bvh.x, bvh.y };
                int bh1[2] = { bvh.z, bvh.w };
                int bl0[2] = { bvl.x, bvl.y };
                int bl1[2] = { bvl.z, bvl.w };
#pragma unroll
                for (int mi = 0; mi < 2; mi++) {
                    mma_bf16(acc[mi][nip * 2],     ah[mi], bh0);
                    mma_bf16(acc[mi][nip * 2],     ah[mi], bl0);
                    mma_bf16(acc[mi][nip * 2],     al[mi], bh0);
                    mma_bf16(acc[mi][nip * 2 + 1], ah[mi], bh1);
                    mma_bf16(acc[mi][nip * 2 + 1], ah[mi], bl1);
                    mma_bf16(acc[mi][nip * 2 + 1], al[mi], bh1);
                }
            }
        }
        if (++stg_idx == 3) stg_idx = 0;
    }

    // Epilogue: provisional spikes; uncertain coords pushed to fixup list.
    const int tt = o0 / 768;
    const int hbase = ((o0 % 768) >> 6) + (warpN >> 1);
    const int bh = (m0 >> 10) * H_ + hbase;
    const int nb = (m0 & 1023) + warpM * 32;
#pragma unroll
    for (int mi = 0; mi < 2; mi++) {
#pragma unroll
        for (int ni = 0; ni < 4; ni++) {
            const int col = warpN * 32 + (ni >> 1) * 16 + (ni & 1) * 8 + tig * 2;
            const int d = col & 63;
            int8_t sv[4];
            bool unc[4];
            bool any_unc = false;
#pragma unroll
            for (int e = 0; e < 4; e++) {
                float v = acc[mi][ni][e];
                sv[e] = (int8_t)spike_of(v);
                unc[e] = (fabsf(v - 0.5f) < MARGIN) || (fabsf(v + 0.5f) < MARGIN);
                any_unc |= unc[e];
            }
            if (__any_sync(0xffffffffu, any_unc)) {
#pragma unroll
                for (int e = 0; e < 4; e++) {
                    unsigned msk = __ballot_sync(0xffffffffu, unc[e]);
                    if (msk) {
                        int ldr = __ffs(msk) - 1;
                        int base = 0;
                        if (lane == ldr) base = atomicAdd(&g_nfix, __popc(msk));
                        base = __shfl_sync(0xffffffffu, base, ldr);
                        if (unc[e]) {
                            int mg = m0 + warpM * 32 + mi * 16 + g + ((e >> 1) ? 8 : 0);
                            int og = o0 + col + (e & 1);
                            int pos = base + __popc(msk & ((1u << lane) - 1));
                            if (pos < FIXCAP) g_fix_list[pos] = mg * O3_ + og;
                        }
                    }
                }
            }
            int n1 = nb + mi * 16 + g;
            if (tt == 2) {
                char2 v0, v1;
                v0.x = sv[0]; v0.y = sv[1];
                v1.x = sv[2]; v1.y = sv[3];
                *(char2*)&g_spk[2][bh][n1][d]     = v0;
                *(char2*)&g_spk[2][bh][n1 + 8][d] = v1;
            } else {
                __nv_bfloat162 b0p, b1p;
                b0p.x = __float2bfloat16((float)sv[0]);
                b0p.y = __float2bfloat16((float)sv[1]);
                b1p.x = __float2bfloat16((float)sv[2]);
                b1p.y = __float2bfloat16((float)sv[3]);
                *(__nv_bfloat162*)&g_qkb[tt][bh][n1][d]     = b0p;
                *(__nv_bfloat162*)&g_qkb[tt][bh][n1 + 8][d] = b1p;
            }
        }
    }
}

// ---------------------------------------------------------------------------
// Kernel 3: fixup — exact fp32 warp-dots; writes bf16 for q/k, int8 for v.
// ---------------------------------------------------------------------------
__global__ void __launch_bounds__(256) fixup_kernel(const float* __restrict__ x,
                                                    const float* __restrict__ w) {
    const int lane = threadIdx.x & 31;
    const int gw = (blockIdx.x * blockDim.x + threadIdx.x) >> 5;
    const int nw = (gridDim.x * blockDim.x) >> 5;
    int nfix = g_nfix;
    if (nfix > FIXCAP) nfix = FIXCAP;

    for (int i = gw; i < nfix; i += nw) {
        int code = g_fix_list[i];
        int m = code / O3_;
        int o = code - m * O3_;
        const float4* xp = (const float4*)(x + (size_t)m * C_);
        const float4* wp = (const float4*)(w + (size_t)o * C_);
        float s = 0.0f;
#pragma unroll
        for (int c = 0; c < 6; c++) {
            float4 xv = xp[lane + c * 32];
            float4 wv = wp[lane + c * 32];
            s += xv.x * wv.x + xv.y * wv.y + xv.z * wv.z + xv.w * wv.w;
        }
#pragma unroll
        for (int off = 16; off; off >>= 1)
            s += __shfl_xor_sync(0xffffffffu, s, off);
        if (lane == 0) {
            int tt = o / 768, rem = o - tt * 768;
            int bh = (m >> 10) * H_ + (rem >> 6);
            int sp = spike_of(s);
            if (tt == 2) g_spk[2][bh][m & 1023][rem & 63] = (int8_t)sp;
            else g_qkb[tt][bh][m & 1023][rem & 63] = __float2bfloat16((float)sp);
        }
    }
}

// ---------------------------------------------------------------------------
// Kernel 4 (profiled): FUSED attention, bf16 HMMA logits + smem-staged K.
// 8 warps in two 4-warp groups; group g covers K-chunks g*8..g*8+7.
// K tiles staged via cp.async into 144B-row-strided buffers (conflict-free
// B-fragment LDS). ONE __syncthreads per iteration.
// smem: ssq 8KB @0; ssk 4 bufs x 9216B @8192; sd 64x1040 @45056.
// ---------------------------------------------------------------------------
#define KROW   144
#define KBUF   (64 * KROW)          // 9216
#define ATTN_DSMEM (8192 + 4 * KBUF + 64 * 1040)   // 111616

__global__ void __launch_bounds__(256) attn_kernel() {
    extern __shared__ char dyn[];
    uint32_t sbase;
    asm("{ .reg .u64 tmp; cvta.to.shared.u64 tmp, %1; cvt.u32.u64 %0, tmp; }"
        : "=r"(sbase) : "l"(dyn));
    char* ssq = dyn;
    char* sd  = dyn + 8192 + 4 * KBUF;
    const int t = threadIdx.x;
    const int lane = t & 31, wid = t >> 5;
    const int wg = wid >> 2;          // K-chunk group 0/1
    const int tg = t & 127;           // thread-in-group
    const int wrp2 = wid & 3;         // warp-in-group (row block)
    const int gid = lane >> 2, tig = lane & 3;
    const int bh = blockIdx.y, n0 = blockIdx.x * 64;
    const int b = bh / H_, h = bh - b * H_;

    {   // ssq: 8KB bf16 q tile
        const int4* src = (const int4*)&g_qkb[0][bh][n0][0];
        ((int4*)ssq)[t] = src[t];
        ((int4*)ssq)[t + 256] = src[t + 256];
    }

    // K-chunk staging: 8KB source -> 144B-strided buffer (group-local).
#define KPRE(mc, buf) do {                                                     \
    const char* _src = (const char*)&g_qkb[1][bh][(mc) * 64][0];               \
    uint32_t _dst = sbase + 8192 + (wg * 2 + (buf)) * KBUF;                    \
    _Pragma("unroll")                                                          \
    for (int _j = 0; _j < 4; _j++) {                                           \
        int idx = tg + _j * 128;          /* 512 int4 chunks */                \
        int row = idx >> 3, col = idx & 7;                                     \
        asm volatile("cp.async.cg.shared.global [%0], [%1], 16;"               \
                     :: "r"(_dst + row * KROW + col * 16),                     \
                        "l"(_src + row * 128 + col * 16));                     \
    } } while (0)

    KPRE(wg * 8, 0);
    asm volatile("cp.async.commit_group;");
    __syncthreads();

    // A fragments: 4 ks-steps of k16
    int afr[4][4];
#pragma unroll
    for (int ks = 0; ks < 4; ks++) {
        int r = wrp2 * 16 + gid;
        afr[ks][0] = *(const int*)(ssq + r * 128 + ks * 32 + tig * 4);
        afr[ks][1] = *(const int*)(ssq + (r + 8) * 128 + ks * 32 + tig * 4);
        afr[ks][2] = *(const int*)(ssq + r * 128 + ks * 32 + 16 + tig * 4);
        afr[ks][3] = *(const int*)(ssq + (r + 8) * 128 + ks * 32 + 16 + tig * 4);
    }

    for (int i = 0; i < 8; i++) {
        asm volatile("cp.async.wait_group 0;");
        __syncthreads();
        if (i + 1 < 8) {
            KPRE(wg * 8 + i + 1, (i + 1) & 1);
            asm volatile("cp.async.commit_group;");
        }
        const char* ssk = dyn + 8192 + (wg * 2 + (i & 1)) * KBUF;
        const int mc = wg * 8 + i;
#pragma unroll
        for (int c = 0; c < 8; c++) {
            const char* krow = ssk + (c * 8 + gid) * KROW;
            float cc[4] = {0.f, 0.f, 0.f, 0.f};
#pragma unroll
            for (int ks = 0; ks < 4; ks++) {
                int bf[2];
                bf[0] = *(const int*)(krow + ks * 32 + tig * 4);
                bf[1] = *(const int*)(krow + ks * 32 + 16 + tig * 4);
                mma_bf16(cc, afr[ks], bf);
            }
            int row = wrp2 * 16 + gid;
            int col = mc * 64 + c * 8 + tig * 2;
            char2 lo; lo.x = (char)(int)cc[0]; lo.y = (char)(int)cc[1];
            char2 hi; hi.x = (char)(int)cc[2]; hi.y = (char)(int)cc[3];
            *(char2*)(sd + row * 1040 + col)       = lo;
            *(char2*)(sd + (row + 8) * 1040 + col) = hi;
        }
    }
    __syncthreads();

    // Phase 2: 8 warps x 8 rows (integer reject; exact path is rare)
    for (int r = 0; r < 8; r++) {
        const int row = wid * 8 + r;
        const char* rp = sd + row * 1040;
        int4 v0 = ((const int4*)rp)[lane];
        int4 v1 = ((const int4*)rp)[lane + 32];
        int words[8] = {v0.x, v0.y, v0.z, v0.w, v1.x, v1.y, v1.z, v1.w};

        int mxw = words[0];
#pragma unroll
        for (int wi = 1; wi < 8; wi++) mxw = __vmaxs4(mxw, words[wi]);
#pragma unroll
        for (int off = 16; off; off >>= 1)
            mxw = __vmaxs4(mxw, __shfl_xor_sync(0xffffffffu, mxw, off));
        int lmax = max(max((mxw << 24) >> 24, (mxw << 16) >> 24),
                       max((mxw << 8) >> 24,  mxw >> 24));

        // strong reject: >=22 elems within 24 of max -> s > 2 -> no spike
        int t24 = lmax - 24;
        int tspl = (t24 & 0xff) * 0x01010101;
        int cnt = 0;
#pragma unroll
        for (int wi = 0; wi < 8; wi++)
            cnt += __popc(__vcmpges4(words[wi], tspl));
#pragma unroll
        for (int off = 16; off; off >>= 1)
            cnt += __shfl_xor_sync(0xffffffffu, cnt, off);

        int* dst = (int*)&g_s[b * N_ + n0 + row][h * D_];
        if (cnt >= 22 * 8) {
            if (lane < 16) dst[lane] = 0;
            continue;
        }

        float s = 0.0f;
        int larg = 0x7fffffff;
#pragma unroll
        for (int wi = 0; wi < 8; wi++) {
            int colbase = (wi < 4) ? (lane * 16 + wi * 4)
                                   : (512 + lane * 16 + (wi - 4) * 4);
#pragma unroll
            for (int j = 0; j < 4; j++) {
                int val = (words[wi] << (24 - 8 * j)) >> 24;
                s += expf(0.125f * (float)(val - lmax));
                if (val == lmax) larg = min(larg, colbase + j);
            }
        }
#pragma unroll
        for (int off = 16; off; off >>= 1) {
            s    += __shfl_xor_sync(0xffffffffu, s, off);
            larg  = min(larg, __shfl_xor_sync(0xffffffffu, larg, off));
        }
        float p = 1.0f / s;
        bool spk = (p + 0.5f) >= 1.0f;
        if (spk) {
            const int* src = (const int*)&g_spk[2][bh][larg][0];
            if (lane < 16) dst[lane] = src[lane];
            if (lane == 0) g_flag[b * N_ + n0 + row] = 1;
        } else {
            if (lane < 16) dst[lane] = 0;
        }
    }
}

// ---------------------------------------------------------------------------
// Kernel 5: output projection (fp32 exact) + final IF, zero-tile skip.
// ---------------------------------------------------------------------------
__global__ void __launch_bounds__(256) proj_kernel(const float* __restrict__ wp,
                                                   float* __restrict__ out) {
    __shared__ float As[16][64];
    __shared__ float Bs[16][64];
    __shared__ int s_any;
    const int t = threadIdx.x;
    const int tx = t & 15, ty = t >> 4;
    const int m0 = blockIdx.y * 64, o0 = blockIdx.x * 64;
    const int lr = t >> 2, lc = (t & 3) * 4;

    if (t == 0) s_any = 0;
    __syncthreads();
    if (t < 64 && g_flag[m0 + t]) s_any = 1;
    __syncthreads();
    if (!s_any) {
        float4 z = make_float4(0.f, 0.f, 0.f, 0.f);
#pragma unroll
        for (int p = 0; p < 4; p++)
            *(float4*)&out[(size_t)(m0 + lr) * 768 + o0 + (t & 3) * 4 + p * 16] = z;
        return;
    }

    float acc[4][4] = {};
    for (int k0 = 0; k0 < 768; k0 += 16) {
        int    aw = *(const int*)&g_s[m0 + lr][k0 + lc];
        float4 bv = *(const float4*)&wp[(size_t)(o0 + lr) * 768 + k0 + lc];
        __syncthreads();
        As[lc + 0][lr] = (float)((aw << 24) >> 24);
        As[lc + 1][lr] = (float)((aw << 16) >> 24);
        As[lc + 2][lr] = (float)((aw << 8)  >> 24);
        As[lc + 3][lr] = (float)( aw        >> 24);
        Bs[lc + 0][lr] = bv.x; Bs[lc + 1][lr] = bv.y;
        Bs[lc + 2][lr] = bv.z; Bs[lc + 3][lr] = bv.w;
        __syncthreads();
#pragma unroll
        for (int k = 0; k < 16; k++) {
            float4 a = *(const float4*)&As[k][ty * 4];
            float4 b = *(const float4*)&Bs[k][tx * 4];
            float ar[4] = {a.x, a.y, a.z, a.w};
            float br[4] = {b.x, b.y, b.z, b.w};
#pragma unroll
            for (int i = 0; i < 4; i++)
#pragma unroll
                for (int j = 0; j < 4; j++)
                    acc[i][j] = fmaf(ar[i], br[j], acc[i][j]);
        }
    }
#pragma unroll
    for (int i = 0; i < 4; i++) {
        int m = m0 + ty * 4 + i;
#pragma unroll
        for (int j = 0; j < 4; j++) {
            int o = o0 + tx * 4 + j;
            out[(size_t)m * 768 + o] = (float)spike_of(acc[i][j]);
        }
    }
}

// ---------------------------------------------------------------------------
extern "C" void kernel_launch(void* const* d_in, const int* in_sizes, int n_in,
                              void* d_out, int out_size) {
    const float* x      = (const float*)d_in[0];
    const float* w_qkv  = (const float*)d_in[1];
    const float* w_proj = (const float*)d_in[2];
    float* out = (float*)d_out;

    cudaFuncSetAttribute(qkv_mma_kernel,
                         cudaFuncAttributeMaxDynamicSharedMemorySize, QKV_DSMEM);
    cudaFuncSetAttribute(attn_kernel,
                         cudaFuncAttributeMaxDynamicSharedMemorySize, ATTN_DSMEM);

    prep_kernel<<<3936, 256>>>(x, w_qkv);                 // launch 1
    qkv_mma_kernel<<<dim3(18, 64), 512, QKV_DSMEM>>>();   // launch 2
    fixup_kernel<<<512, 256>>>(x, w_qkv);                 // launch 3
    attn_kernel<<<dim3(16, 96), 256, ATTN_DSMEM>>>();     // launch 4 (profiled)
    proj_kernel<<<dim3(12, 128), 256>>>(w_proj, out);     // launch 5
}